// round 2
// baseline (speedup 1.0000x reference)
#include <cuda_runtime.h>
#include <cuda_bf16.h>
#include <stdint.h>

using bf16 = __nv_bfloat16;

static constexpr int Tt   = 2048;
static constexpr int HID  = 4096;
static constexpr int NH   = 16;
static constexpr int HD   = 256;
static constexpr int QKVN = 12288;  // q(4096) + k(4096) + v(4096)

// ---------------------------------------------------------------------------
// Scratch (static __device__ arrays — the sanctioned no-alloc workaround)
// ---------------------------------------------------------------------------
__device__ float g_qkv[(size_t)Tt * QKVN];                       // 100 MB
__device__ bf16  g_Hh[(size_t)Tt * HID],  g_Hl[(size_t)Tt * HID];
__device__ bf16  g_Wh[(size_t)HID * QKVN], g_Wl[(size_t)HID * QKVN];
__device__ bf16  g_Qh[(size_t)NH * Tt * HD], g_Ql[(size_t)NH * Tt * HD];
__device__ bf16  g_Kth[(size_t)NH * HD * Tt], g_Ktl[(size_t)NH * HD * Tt]; // [h][d][t]
__device__ bf16  g_Vh[(size_t)NH * Tt * HD], g_Vl[(size_t)NH * Tt * HD];
__device__ float g_S[(size_t)NH * Tt * Tt];                      // 268 MB
__device__ bf16  g_Ph[(size_t)NH * Tt * Tt], g_Pl[(size_t)NH * Tt * Tt];
__device__ float g_att[(size_t)Tt * HID];
__device__ bf16  g_Ah[(size_t)Tt * HID], g_Al[(size_t)Tt * HID];
__device__ bf16  g_Woh[(size_t)HID * HID], g_Wol[(size_t)HID * HID];

// ---------------------------------------------------------------------------
// MMA / ldmatrix primitives
// ---------------------------------------------------------------------------
__device__ __forceinline__ void ldmx4(uint32_t* r, uint32_t addr) {
    asm volatile("ldmatrix.sync.aligned.m8n8.x4.shared.b16 {%0,%1,%2,%3}, [%4];"
                 : "=r"(r[0]), "=r"(r[1]), "=r"(r[2]), "=r"(r[3]) : "r"(addr));
}
__device__ __forceinline__ void ldmx4t(uint32_t* r, uint32_t addr) {
    asm volatile("ldmatrix.sync.aligned.m8n8.x4.trans.shared.b16 {%0,%1,%2,%3}, [%4];"
                 : "=r"(r[0]), "=r"(r[1]), "=r"(r[2]), "=r"(r[3]) : "r"(addr));
}
__device__ __forceinline__ void mma16816(float* c, const uint32_t* a, const uint32_t* b) {
    asm volatile("mma.sync.aligned.m16n8k16.row.col.f32.bf16.bf16.f32 "
                 "{%0,%1,%2,%3},{%4,%5,%6,%7},{%8,%9},{%0,%1,%2,%3};"
                 : "+f"(c[0]), "+f"(c[1]), "+f"(c[2]), "+f"(c[3])
                 : "r"(a[0]), "r"(a[1]), "r"(a[2]), "r"(a[3]), "r"(b[0]), "r"(b[1]));
}

__device__ __forceinline__ void split_store(float v, bf16* hp, bf16* lp) {
    bf16 hb = __float2bfloat16_rn(v);
    *hp = hb;
    *lp = __float2bfloat16_rn(v - __bfloat162float(hb));
}

// ---------------------------------------------------------------------------
// Generic bf16x3 GEMM: C(fp32) = A @ B, A[M][K] (k-major, hi/lo), B[K][N]
// (n-major rows, hi/lo). Accurate to ~2^-18 relative (fp32-class).
// BM = BN = 128, BK = 32, 256 threads (8 warps, 2x4, warp tile 64x32).
// mode 0: dense.  mode 1: skip tiles with n_tile > m_tile (causal scores).
// mode 2: limit K to (m_tile+1)*128 (causal PV).
// All dims are multiples of the tile sizes for this problem (no bounds checks).
// ---------------------------------------------------------------------------
__global__ void __launch_bounds__(256, 1)
gemm3_kernel(const bf16* __restrict__ Ah, const bf16* __restrict__ Al,
             const bf16* __restrict__ Bh, const bf16* __restrict__ Bl,
             float* __restrict__ C,
             int M, int N, int K, int lda, int ldb, int ldc,
             long long sA, long long sB, long long sC, int mode)
{
    if (mode == 1 && blockIdx.x > blockIdx.y) return;
    const int kmax = (mode == 2) ? min(K, ((int)blockIdx.y + 1) * 128) : K;

    Ah += (size_t)blockIdx.z * sA;  Al += (size_t)blockIdx.z * sA;
    Bh += (size_t)blockIdx.z * sB;  Bl += (size_t)blockIdx.z * sB;
    C  += (size_t)blockIdx.z * sC;

    const int m0 = blockIdx.y * 128;
    const int n0 = blockIdx.x * 128;

    __shared__ uint4 sAh[512], sAl[512], sBh[512], sBl[512];

    const int tid  = threadIdx.x;
    const int lane = tid & 31;
    const int wid  = tid >> 5;
    const int wm   = wid & 1;   // 2 warps over M (64 rows each)
    const int wn   = wid >> 1;  // 4 warps over N (32 cols each)

    // global -> smem mapping (16B chunks)
    const int ar  = tid >> 1;         // A row 0..127
    const int ac  = tid & 1;          // A chunk base (c = ac + 2j, j=0..1)
    const int br  = tid >> 3;         // B row (k) 0..31
    const int bc  = tid & 7;          // B chunk base (c = bc + 8j)

    const uint32_t uAh = (uint32_t)__cvta_generic_to_shared(sAh);
    const uint32_t uAl = (uint32_t)__cvta_generic_to_shared(sAl);
    const uint32_t uBh = (uint32_t)__cvta_generic_to_shared(sBh);
    const uint32_t uBl = (uint32_t)__cvta_generic_to_shared(sBl);

    const int rl    = lane & 15;  // row-in-16 for ldmatrix addressing
    const int chalf = lane >> 4;  // 0/1: which 8-col half

    float acc[4][4][4];
    #pragma unroll
    for (int a = 0; a < 4; a++)
        #pragma unroll
        for (int b = 0; b < 4; b++)
            #pragma unroll
            for (int c = 0; c < 4; c++) acc[a][b][c] = 0.f;

    const bf16* pAh = Ah + (size_t)(m0 + ar) * lda;
    const bf16* pAl = Al + (size_t)(m0 + ar) * lda;
    const bf16* pBh = Bh + (size_t)br * ldb + n0;
    const bf16* pBl = Bl + (size_t)br * ldb + n0;

    for (int k0 = 0; k0 < kmax; k0 += 32) {
        // ---- load tiles (coalesced 16B; XOR swizzle for conflict-free ldmatrix)
        #pragma unroll
        for (int j = 0; j < 2; j++) {
            const int c  = ac + 2 * j;                  // 0..3
            const int sc = c ^ ((ar >> 1) & 3);
            sAh[ar * 4 + sc] = *(const uint4*)(pAh + k0 + c * 8);
            sAl[ar * 4 + sc] = *(const uint4*)(pAl + k0 + c * 8);
        }
        #pragma unroll
        for (int j = 0; j < 2; j++) {
            const int c  = bc + 8 * j;                  // 0..15
            const int sc = c ^ (br & 7);
            sBh[br * 16 + sc] = *(const uint4*)(pBh + (size_t)k0 * ldb + c * 8);
            sBl[br * 16 + sc] = *(const uint4*)(pBl + (size_t)k0 * ldb + c * 8);
        }
        __syncthreads();

        #pragma unroll
        for (int ks = 0; ks < 2; ks++) {
            uint32_t fah[4][4], fal[4][4];
            #pragma unroll
            for (int mi = 0; mi < 4; mi++) {
                const int row = wm * 64 + mi * 16 + rl;
                const int sc  = (ks * 2 + chalf) ^ ((row >> 1) & 3);
                const uint32_t off = (uint32_t)(row * 64 + sc * 16);
                ldmx4(fah[mi], uAh + off);
                ldmx4(fal[mi], uAl + off);
            }
            uint32_t fbh[4][2], fbl[4][2];
            #pragma unroll
            for (int j = 0; j < 2; j++) {
                const int krow = ks * 16 + rl;
                const int sc   = (wn * 4 + j * 2 + chalf) ^ (krow & 7);
                const uint32_t off = (uint32_t)(krow * 256 + sc * 16);
                uint32_t t4[4];
                ldmx4t(t4, uBh + off);
                fbh[j*2][0] = t4[0]; fbh[j*2][1] = t4[1];
                fbh[j*2+1][0] = t4[2]; fbh[j*2+1][1] = t4[3];
                ldmx4t(t4, uBl + off);
                fbl[j*2][0] = t4[0]; fbl[j*2][1] = t4[1];
                fbl[j*2+1][0] = t4[2]; fbl[j*2+1][1] = t4[3];
            }
            #pragma unroll
            for (int mi = 0; mi < 4; mi++)
                #pragma unroll
                for (int ni = 0; ni < 4; ni++) {
                    mma16816(acc[mi][ni], fah[mi], fbh[ni]);  // hi*hi
                    mma16816(acc[mi][ni], fah[mi], fbl[ni]);  // hi*lo
                    mma16816(acc[mi][ni], fal[mi], fbh[ni]);  // lo*hi
                }
        }
        __syncthreads();
    }

    #pragma unroll
    for (int mi = 0; mi < 4; mi++)
        #pragma unroll
        for (int ni = 0; ni < 4; ni++) {
            const int r = m0 + wm * 64 + mi * 16 + (lane >> 2);
            const int c = n0 + wn * 32 + ni * 8 + (lane & 3) * 2;
            *(float2*)&C[(size_t)r * ldc + c] =
                make_float2(acc[mi][ni][0], acc[mi][ni][1]);
            *(float2*)&C[(size_t)(r + 8) * ldc + c] =
                make_float2(acc[mi][ni][2], acc[mi][ni][3]);
        }
}

// ---------------------------------------------------------------------------
// fp32 -> (hi, lo) bf16 split
// ---------------------------------------------------------------------------
__global__ void split_kernel(const float* __restrict__ x,
                             bf16* __restrict__ h, bf16* __restrict__ l, size_t n)
{
    size_t i = (size_t)blockIdx.x * blockDim.x + threadIdx.x;
    const size_t stride = (size_t)gridDim.x * blockDim.x;
    for (; i < n; i += stride) split_store(x[i], h + i, l + i);
}

// ---------------------------------------------------------------------------
// Block reduction helper: 256 threads, smem tree to 32 then warp shuffle.
// ---------------------------------------------------------------------------
template <bool MAX>
__device__ __forceinline__ float bred256(float x, float* red, int tid) {
    red[tid] = x; __syncthreads();
    if (tid < 128) {
        float o = red[tid + 128];
        red[tid] = MAX ? fmaxf(red[tid], o) : red[tid] + o;
    }
    __syncthreads();
    if (tid < 64) {
        float o = red[tid + 64];
        red[tid] = MAX ? fmaxf(red[tid], o) : red[tid] + o;
    }
    __syncthreads();
    if (tid < 32) {
        float v = MAX ? fmaxf(red[tid], red[tid + 32]) : red[tid] + red[tid + 32];
        #pragma unroll
        for (int s = 16; s > 0; s >>= 1) {
            float o = __shfl_down_sync(0xffffffffu, v, s);
            v = MAX ? fmaxf(v, o) : v + o;
        }
        if (tid == 0) red[0] = v;
    }
    __syncthreads();
    float r = red[0];
    __syncthreads();
    return r;
}

// ---------------------------------------------------------------------------
// Fused RMSNorm + NeoX RoPE; writes split Q [h][t][d], K^T [h][d][t], V [h][t][d]
// One block per (t, h), 256 threads (= D).
// ---------------------------------------------------------------------------
__global__ void __launch_bounds__(256) normrope_kernel(
    const float* __restrict__ qkv, const int* __restrict__ positions,
    const float* __restrict__ qw, const float* __restrict__ kw,
    bf16* __restrict__ Qh, bf16* __restrict__ Ql,
    bf16* __restrict__ Kth, bf16* __restrict__ Ktl,
    bf16* __restrict__ Vh, bf16* __restrict__ Vl)
{
    const int t = blockIdx.x, h = blockIdx.y, d = threadIdx.x;
    const float* base = qkv + (size_t)t * QKVN;
    const float q = base[h * HD + d];
    const float k = base[HID + h * HD + d];
    const float v = base[2 * HID + h * HD + d];

    __shared__ float red[256];
    const float rq = rsqrtf(bred256<false>(q * q, red, d) * (1.f / HD) + 1e-6f);
    const float rk = rsqrtf(bred256<false>(k * k, red, d) * (1.f / HD) + 1e-6f);
    const float rv = rsqrtf(bred256<false>(v * v, red, d) * (1.f / HD) + 1e-6f);
    const float qn = q * rq * qw[d];
    const float kn = k * rk * kw[d];
    const float vn = v * rv;

    __shared__ float shq[256], shk[256];
    shq[d] = qn; shk[d] = kn; __syncthreads();

    const int j = d & 127;
    double invf = pow(10000.0, -(double)j / 128.0);
    double ang = (double)positions[t] * invf;
    const double tp = 6.283185307179586476925286766559;
    ang -= tp * floor(ang / tp);
    const float c = cosf((float)ang), s = sinf((float)ang);

    const float x1q = shq[j], x2q = shq[j + 128];
    const float x1k = shk[j], x2k = shk[j + 128];
    const float qr = (d < 128) ? (x1q * c - x2q * s) : (x2q * c + x1q * s);
    const float kr = (d < 128) ? (x1k * c - x2k * s) : (x2k * c + x1k * s);

    const size_t qi = ((size_t)h * Tt + t) * HD + d;
    split_store(qr, Qh + qi, Ql + qi);
    const size_t ki = ((size_t)h * HD + d) * Tt + t;   // transposed K
    split_store(kr, Kth + ki, Ktl + ki);
    split_store(vn, Vh + qi, Vl + qi);
}

// ---------------------------------------------------------------------------
// Causal row softmax; reads S[h][t][0..t], writes split probs.
// Only writes up to the k-tile boundary the PV GEMM (mode 2) will read:
// limit = ((t/128)+1)*128.  Entries in [t+1, limit) are zeroed.
// ---------------------------------------------------------------------------
__global__ void __launch_bounds__(256) softmax_kernel(
    const float* __restrict__ S, bf16* __restrict__ Ph, bf16* __restrict__ Pl)
{
    const int t = blockIdx.x, h = blockIdx.y;
    const size_t base = ((size_t)h * Tt + t) * Tt;
    const float* row = S + base;
    const int n = t + 1;
    const int limit = ((t >> 7) + 1) << 7;   // k-tiles PV actually reads
    const int tid = threadIdx.x;
    __shared__ float red[256];

    float mx = -3.4e38f;
    for (int i = tid; i < n; i += 256) mx = fmaxf(mx, row[i]);
    mx = bred256<true>(mx, red, tid);

    float sum = 0.f;
    for (int i = tid; i < n; i += 256) sum += expf(row[i] - mx);
    sum = bred256<false>(sum, red, tid);
    const float inv = 1.f / sum;

    for (int i = tid; i < limit; i += 256) {
        const float p = (i < n) ? expf(row[i] - mx) * inv : 0.f;
        split_store(p, Ph + base + i, Pl + base + i);
    }
}

// ---------------------------------------------------------------------------
// Launch
// ---------------------------------------------------------------------------
extern "C" void kernel_launch(void* const* d_in, const int* in_sizes, int n_in,
                              void* d_out, int out_size)
{
    const float* hidden    = (const float*)d_in[0];
    const int*   positions = (const int*)d_in[1];
    const float* w_qkv     = (const float*)d_in[2];
    const float* w_o       = (const float*)d_in[3];
    const float* qw        = (const float*)d_in[4];
    const float* kw        = (const float*)d_in[5];
    float* out = (float*)d_out;

    float *qkv, *S, *att;
    bf16 *Hh, *Hl, *Wh, *Wl, *Qh, *Ql, *Kth, *Ktl, *Vh, *Vl, *Ph, *Pl, *Ah, *Al, *Woh, *Wol;
    cudaGetSymbolAddress((void**)&qkv, g_qkv);
    cudaGetSymbolAddress((void**)&S,   g_S);
    cudaGetSymbolAddress((void**)&att, g_att);
    cudaGetSymbolAddress((void**)&Hh,  g_Hh);   cudaGetSymbolAddress((void**)&Hl,  g_Hl);
    cudaGetSymbolAddress((void**)&Wh,  g_Wh);   cudaGetSymbolAddress((void**)&Wl,  g_Wl);
    cudaGetSymbolAddress((void**)&Qh,  g_Qh);   cudaGetSymbolAddress((void**)&Ql,  g_Ql);
    cudaGetSymbolAddress((void**)&Kth, g_Kth);  cudaGetSymbolAddress((void**)&Ktl, g_Ktl);
    cudaGetSymbolAddress((void**)&Vh,  g_Vh);   cudaGetSymbolAddress((void**)&Vl,  g_Vl);
    cudaGetSymbolAddress((void**)&Ph,  g_Ph);   cudaGetSymbolAddress((void**)&Pl,  g_Pl);
    cudaGetSymbolAddress((void**)&Ah,  g_Ah);   cudaGetSymbolAddress((void**)&Al,  g_Al);
    cudaGetSymbolAddress((void**)&Woh, g_Woh);  cudaGetSymbolAddress((void**)&Wol, g_Wol);

    // 1. split inputs / weights to bf16 hi/lo
    split_kernel<<<512, 256>>>(hidden, Hh, Hl, (size_t)Tt * HID);
    split_kernel<<<2048, 256>>>(w_qkv, Wh, Wl, (size_t)HID * QKVN);
    split_kernel<<<1024, 256>>>(w_o, Woh, Wol, (size_t)HID * HID);

    // 2. qkv = hidden @ w_qkv
    gemm3_kernel<<<dim3(QKVN / 128, Tt / 128, 1), 256>>>(
        Hh, Hl, Wh, Wl, qkv, Tt, QKVN, HID, HID, QKVN, QKVN, 0, 0, 0, 0);

    // 3. rmsnorm + rope, write split Q / K^T / V
    normrope_kernel<<<dim3(Tt, NH), 256>>>(qkv, positions, qw, kw,
                                           Qh, Ql, Kth, Ktl, Vh, Vl);

    // 4. scores[h] = Q[h] @ K[h]^T  (skip tiles above diagonal)
    gemm3_kernel<<<dim3(Tt / 128, Tt / 128, NH), 256>>>(
        Qh, Ql, Kth, Ktl, S, Tt, Tt, HD, HD, Tt, Tt,
        (long long)Tt * HD, (long long)HD * Tt, (long long)Tt * Tt, 1);

    // 5. causal softmax -> split probs
    softmax_kernel<<<dim3(Tt, NH), 256>>>(S, Ph, Pl);

    // 6. attn[h] = P[h] @ V[h]  (k-tiles limited by diagonal)
    gemm3_kernel<<<dim3(HD / 128, Tt / 128, NH), 256>>>(
        Ph, Pl, Vh, Vl, att, Tt, HD, Tt, Tt, HD, HID,
        (long long)Tt * Tt, (long long)Tt * HD, (long long)HD, 2);

    // 7. out = attn @ w_o
    split_kernel<<<512, 256>>>(att, Ah, Al, (size_t)Tt * HID);
    gemm3_kernel<<<dim3(HID / 128, Tt / 128, 1), 256>>>(
        Ah, Al, Woh, Wol, out, Tt, HID, HID, HID, HID, HID, 0, 0, 0, 0);
}

// round 4
// speedup vs baseline: 1.4913x; 1.4913x over previous
#include <cuda_runtime.h>
#include <cuda_bf16.h>
#include <stdint.h>

using bf16 = __nv_bfloat16;

static constexpr int Tt   = 2048;
static constexpr int HID  = 4096;
static constexpr int NH   = 16;
static constexpr int HD   = 256;
static constexpr int QKVN = 12288;  // q(4096) + k(4096) + v(4096)

static constexpr int STAGES     = 3;
static constexpr int SMEM_BYTES = STAGES * 32768;    // 96 KB dynamic

// ---------------------------------------------------------------------------
// Scratch (static __device__ arrays — the sanctioned no-alloc workaround)
// ---------------------------------------------------------------------------
__device__ float g_qkv[(size_t)Tt * QKVN];                       // 100 MB
__device__ bf16  g_Hh[(size_t)Tt * HID],  g_Hl[(size_t)Tt * HID];
__device__ bf16  g_Wh[(size_t)HID * QKVN], g_Wl[(size_t)HID * QKVN];
__device__ bf16  g_Qh[(size_t)NH * Tt * HD], g_Ql[(size_t)NH * Tt * HD];
__device__ bf16  g_Kth[(size_t)NH * HD * Tt], g_Ktl[(size_t)NH * HD * Tt]; // [h][d][t]
__device__ bf16  g_Vh[(size_t)NH * Tt * HD], g_Vl[(size_t)NH * Tt * HD];
__device__ float g_S[(size_t)NH * Tt * Tt];                      // 268 MB
__device__ bf16  g_Ph[(size_t)NH * Tt * Tt], g_Pl[(size_t)NH * Tt * Tt];
__device__ float g_att[(size_t)Tt * HID];
__device__ bf16  g_Ah[(size_t)Tt * HID], g_Al[(size_t)Tt * HID];
__device__ bf16  g_Woh[(size_t)HID * HID], g_Wol[(size_t)HID * HID];

// ---------------------------------------------------------------------------
// MMA / ldmatrix / cp.async primitives
// ---------------------------------------------------------------------------
__device__ __forceinline__ void ldmx4(uint32_t* r, uint32_t addr) {
    asm volatile("ldmatrix.sync.aligned.m8n8.x4.shared.b16 {%0,%1,%2,%3}, [%4];"
                 : "=r"(r[0]), "=r"(r[1]), "=r"(r[2]), "=r"(r[3]) : "r"(addr));
}
__device__ __forceinline__ void ldmx4t(uint32_t* r, uint32_t addr) {
    asm volatile("ldmatrix.sync.aligned.m8n8.x4.trans.shared.b16 {%0,%1,%2,%3}, [%4];"
                 : "=r"(r[0]), "=r"(r[1]), "=r"(r[2]), "=r"(r[3]) : "r"(addr));
}
__device__ __forceinline__ void mma16816(float* c, const uint32_t* a, const uint32_t* b) {
    asm volatile("mma.sync.aligned.m16n8k16.row.col.f32.bf16.bf16.f32 "
                 "{%0,%1,%2,%3},{%4,%5,%6,%7},{%8,%9},{%0,%1,%2,%3};"
                 : "+f"(c[0]), "+f"(c[1]), "+f"(c[2]), "+f"(c[3])
                 : "r"(a[0]), "r"(a[1]), "r"(a[2]), "r"(a[3]), "r"(b[0]), "r"(b[1]));
}
__device__ __forceinline__ void cpasync16(uint32_t dst, const void* src) {
    asm volatile("cp.async.cg.shared.global [%0], [%1], 16;" :: "r"(dst), "l"(src));
}
__device__ __forceinline__ void cpcommit() {
    asm volatile("cp.async.commit_group;" ::: "memory");
}
template <int N>
__device__ __forceinline__ void cpwait() {
    asm volatile("cp.async.wait_group %0;" :: "n"(N) : "memory");
}

__device__ __forceinline__ void split_store(float v, bf16* hp, bf16* lp) {
    bf16 hb = __float2bfloat16_rn(v);
    *hp = hb;
    *lp = __float2bfloat16_rn(v - __bfloat162float(hb));
}

// ---------------------------------------------------------------------------
// Generic bf16x3 GEMM, 3-stage cp.async pipeline.
// C(fp32) = A @ B; A[M][K] (k-major, hi/lo), B[K][N] (n-major rows, hi/lo).
// BM = BN = 128, BK = 32, 256 threads (8 warps 2x4, warp tile 64x32).
// mode 0: dense.  mode 1: skip tiles with n_tile > m_tile (causal scores).
// mode 2: limit K to (m_tile+1)*128 (causal PV).
// NOTE: every launch in this problem has >= 4 k-tiles, which the unconditional
// commit-group accounting below relies on.
// Stage layout (bytes from dynamic smem base + stage*32768):
//   [0,8K) Ah   [8K,16K) Al   [16K,24K) Bh   [24K,32K) Bl
// ---------------------------------------------------------------------------
__global__ void __launch_bounds__(256, 1)
gemm3_kernel(const bf16* __restrict__ Ah, const bf16* __restrict__ Al,
             const bf16* __restrict__ Bh, const bf16* __restrict__ Bl,
             float* __restrict__ C,
             int M, int N, int K, int lda, int ldb, int ldc,
             long long sA, long long sB, long long sC, int mode)
{
    if (mode == 1 && blockIdx.x > blockIdx.y) return;
    const int kmax = (mode == 2) ? min(K, ((int)blockIdx.y + 1) * 128) : K;

    Ah += (size_t)blockIdx.z * sA;  Al += (size_t)blockIdx.z * sA;
    Bh += (size_t)blockIdx.z * sB;  Bl += (size_t)blockIdx.z * sB;
    C  += (size_t)blockIdx.z * sC;

    const int m0 = blockIdx.y * 128;
    const int n0 = blockIdx.x * 128;

    extern __shared__ uint4 dsm[];
    const uint32_t ubase = (uint32_t)__cvta_generic_to_shared(dsm);

    const int tid  = threadIdx.x;
    const int lane = tid & 31;
    const int wid  = tid >> 5;
    const int wm   = wid & 1;   // 2 warps over M (64 rows each)
    const int wn   = wid >> 1;  // 4 warps over N (32 cols each)

    // global -> smem mapping (16B chunks)
    const int ar  = tid >> 1;         // A row 0..127
    const int ac  = tid & 1;          // A chunk base (c = ac + 2j)
    const int br  = tid >> 3;         // B row (k) 0..31
    const int bc  = tid & 7;          // B chunk base (c = bc + 8j)

    const int rl    = lane & 15;  // row-in-16 for ldmatrix addressing
    const int chalf = lane >> 4;  // 0/1: which 8-col half

    float acc[4][4][4];
    #pragma unroll
    for (int a = 0; a < 4; a++)
        #pragma unroll
        for (int b = 0; b < 4; b++)
            #pragma unroll
            for (int c = 0; c < 4; c++) acc[a][b][c] = 0.f;

    const bf16* pAh = Ah + (size_t)(m0 + ar) * lda;
    const bf16* pAl = Al + (size_t)(m0 + ar) * lda;
    const bf16* pBh = Bh + (size_t)br * ldb + n0;
    const bf16* pBl = Bl + (size_t)br * ldb + n0;

    // precomputed swizzled smem write offsets (bytes, relative to stage base)
    const int sca0 = (ac + 0) ^ ((ar >> 1) & 3);
    const int sca1 = (ac + 2) ^ ((ar >> 1) & 3);
    const uint32_t aoff0 = (uint32_t)(ar * 64 + sca0 * 16);
    const uint32_t aoff1 = (uint32_t)(ar * 64 + sca1 * 16);
    const int scb0 = (bc + 0) ^ (br & 7);
    const int scb1 = (bc + 8) ^ (br & 7);
    const uint32_t boff0 = (uint32_t)(br * 256 + scb0 * 16);
    const uint32_t boff1 = (uint32_t)(br * 256 + scb1 * 16);

    auto load_tile = [&](int stage, int k0) {
        const uint32_t sb = ubase + (uint32_t)stage * 32768u;
        cpasync16(sb         + aoff0, pAh + k0 + (ac + 0) * 8);
        cpasync16(sb         + aoff1, pAh + k0 + (ac + 2) * 8);
        cpasync16(sb + 8192  + aoff0, pAl + k0 + (ac + 0) * 8);
        cpasync16(sb + 8192  + aoff1, pAl + k0 + (ac + 2) * 8);
        const bf16* bhrow = pBh + (size_t)k0 * ldb;
        const bf16* blrow = pBl + (size_t)k0 * ldb;
        cpasync16(sb + 16384 + boff0, bhrow + (bc + 0) * 8);
        cpasync16(sb + 16384 + boff1, bhrow + (bc + 8) * 8);
        cpasync16(sb + 24576 + boff0, blrow + (bc + 0) * 8);
        cpasync16(sb + 24576 + boff1, blrow + (bc + 8) * 8);
    };

    const int nt = kmax >> 5;           // k-tiles (>= 4 for all launches here)

    #pragma unroll
    for (int s = 0; s < STAGES - 1; s++) { load_tile(s, s * 32); cpcommit(); }

    int stage = 0;
    for (int i = 0; i < nt; i++) {
        cpwait<STAGES - 2>();
        __syncthreads();

        const uint32_t sb  = ubase + (uint32_t)stage * 32768u;
        const uint32_t uAh = sb, uAl = sb + 8192, uBh = sb + 16384, uBl = sb + 24576;

        #pragma unroll
        for (int ks = 0; ks < 2; ks++) {
            uint32_t fah[4][4], fal[4][4];
            #pragma unroll
            for (int mi = 0; mi < 4; mi++) {
                const int row = wm * 64 + mi * 16 + rl;
                const int sc  = (ks * 2 + chalf) ^ ((row >> 1) & 3);
                const uint32_t off = (uint32_t)(row * 64 + sc * 16);
                ldmx4(fah[mi], uAh + off);
                ldmx4(fal[mi], uAl + off);
            }
            uint32_t fbh[4][2], fbl[4][2];
            #pragma unroll
            for (int j = 0; j < 2; j++) {
                const int krow = ks * 16 + rl;
                const int sc   = (wn * 4 + j * 2 + chalf) ^ (krow & 7);
                const uint32_t off = (uint32_t)(krow * 256 + sc * 16);
                uint32_t t4[4];
                ldmx4t(t4, uBh + off);
                fbh[j*2][0] = t4[0]; fbh[j*2][1] = t4[1];
                fbh[j*2+1][0] = t4[2]; fbh[j*2+1][1] = t4[3];
                ldmx4t(t4, uBl + off);
                fbl[j*2][0] = t4[0]; fbl[j*2][1] = t4[1];
                fbl[j*2+1][0] = t4[2]; fbl[j*2+1][1] = t4[3];
            }
            #pragma unroll
            for (int mi = 0; mi < 4; mi++)
                #pragma unroll
                for (int ni = 0; ni < 4; ni++) {
                    mma16816(acc[mi][ni], fah[mi], fbh[ni]);  // hi*hi
                    mma16816(acc[mi][ni], fah[mi], fbl[ni]);  // hi*lo
                    mma16816(acc[mi][ni], fal[mi], fbh[ni]);  // lo*hi
                }
        }
        __syncthreads();

        const int nx = i + STAGES - 1;
        if (nx < nt) load_tile(nx % STAGES, nx * 32);
        cpcommit();     // unconditional: keeps wait_group accounting simple

        stage = (stage + 1 == STAGES) ? 0 : stage + 1;
    }

    #pragma unroll
    for (int mi = 0; mi < 4; mi++)
        #pragma unroll
        for (int ni = 0; ni < 4; ni++) {
            const int r = m0 + wm * 64 + mi * 16 + (lane >> 2);
            const int c = n0 + wn * 32 + ni * 8 + (lane & 3) * 2;
            *(float2*)&C[(size_t)r * ldc + c] =
                make_float2(acc[mi][ni][0], acc[mi][ni][1]);
            *(float2*)&C[(size_t)(r + 8) * ldc + c] =
                make_float2(acc[mi][ni][2], acc[mi][ni][3]);
        }
}

// ---------------------------------------------------------------------------
// fp32 -> (hi, lo) bf16 split, vectorized: float4 in, 2x bf16x2 out.
// n must be a multiple of 4 (true for all uses here).
// ---------------------------------------------------------------------------
__global__ void split_kernel(const float* __restrict__ x,
                             bf16* __restrict__ h, bf16* __restrict__ l, size_t n)
{
    const size_t n4 = n >> 2;
    size_t i = (size_t)blockIdx.x * blockDim.x + threadIdx.x;
    const size_t stride = (size_t)gridDim.x * blockDim.x;
    for (; i < n4; i += stride) {
        float4 v = ((const float4*)x)[i];
        bf16 h0 = __float2bfloat16_rn(v.x), h1 = __float2bfloat16_rn(v.y);
        bf16 h2 = __float2bfloat16_rn(v.z), h3 = __float2bfloat16_rn(v.w);
        __nv_bfloat162 hh0(h0, h1), hh1(h2, h3);
        __nv_bfloat162 ll0(__float2bfloat16_rn(v.x - __bfloat162float(h0)),
                           __float2bfloat16_rn(v.y - __bfloat162float(h1)));
        __nv_bfloat162 ll1(__float2bfloat16_rn(v.z - __bfloat162float(h2)),
                           __float2bfloat16_rn(v.w - __bfloat162float(h3)));
        ((__nv_bfloat162*)h)[i * 2]     = hh0;
        ((__nv_bfloat162*)h)[i * 2 + 1] = hh1;
        ((__nv_bfloat162*)l)[i * 2]     = ll0;
        ((__nv_bfloat162*)l)[i * 2 + 1] = ll1;
    }
}

// ---------------------------------------------------------------------------
// Block reduction helper: 256 threads, smem tree to 32 then warp shuffle.
// ---------------------------------------------------------------------------
template <bool MAX>
__device__ __forceinline__ float bred256(float x, float* red, int tid) {
    red[tid] = x; __syncthreads();
    if (tid < 128) {
        float o = red[tid + 128];
        red[tid] = MAX ? fmaxf(red[tid], o) : red[tid] + o;
    }
    __syncthreads();
    if (tid < 64) {
        float o = red[tid + 64];
        red[tid] = MAX ? fmaxf(red[tid], o) : red[tid] + o;
    }
    __syncthreads();
    if (tid < 32) {
        float v = MAX ? fmaxf(red[tid], red[tid + 32]) : red[tid] + red[tid + 32];
        #pragma unroll
        for (int s = 16; s > 0; s >>= 1) {
            float o = __shfl_down_sync(0xffffffffu, v, s);
            v = MAX ? fmaxf(v, o) : v + o;
        }
        if (tid == 0) red[0] = v;
    }
    __syncthreads();
    float r = red[0];
    __syncthreads();
    return r;
}

// ---------------------------------------------------------------------------
// Fused RMSNorm + NeoX RoPE; writes split Q [h][t][d], K^T [h][d][t], V [h][t][d]
// One block per (t, h), 256 threads (= D).
// ---------------------------------------------------------------------------
__global__ void __launch_bounds__(256) normrope_kernel(
    const float* __restrict__ qkv, const int* __restrict__ positions,
    const float* __restrict__ qw, const float* __restrict__ kw,
    bf16* __restrict__ Qh, bf16* __restrict__ Ql,
    bf16* __restrict__ Kth, bf16* __restrict__ Ktl,
    bf16* __restrict__ Vh, bf16* __restrict__ Vl)
{
    const int t = blockIdx.x, h = blockIdx.y, d = threadIdx.x;
    const float* base = qkv + (size_t)t * QKVN;
    const float q = base[h * HD + d];
    const float k = base[HID + h * HD + d];
    const float v = base[2 * HID + h * HD + d];

    __shared__ float red[256];
    const float rq = rsqrtf(bred256<false>(q * q, red, d) * (1.f / HD) + 1e-6f);
    const float rk = rsqrtf(bred256<false>(k * k, red, d) * (1.f / HD) + 1e-6f);
    const float rv = rsqrtf(bred256<false>(v * v, red, d) * (1.f / HD) + 1e-6f);
    const float qn = q * rq * qw[d];
    const float kn = k * rk * kw[d];
    const float vn = v * rv;

    __shared__ float shq[256], shk[256];
    shq[d] = qn; shk[d] = kn; __syncthreads();

    const int j = d & 127;
    double invf = pow(10000.0, -(double)j / 128.0);
    double ang = (double)positions[t] * invf;
    const double tp = 6.283185307179586476925286766559;
    ang -= tp * floor(ang / tp);
    const float c = cosf((float)ang), s = sinf((float)ang);

    const float x1q = shq[j], x2q = shq[j + 128];
    const float x1k = shk[j], x2k = shk[j + 128];
    const float qr = (d < 128) ? (x1q * c - x2q * s) : (x2q * c + x1q * s);
    const float kr = (d < 128) ? (x1k * c - x2k * s) : (x2k * c + x1k * s);

    const size_t qi = ((size_t)h * Tt + t) * HD + d;
    split_store(qr, Qh + qi, Ql + qi);
    const size_t ki = ((size_t)h * HD + d) * Tt + t;   // transposed K
    split_store(kr, Kth + ki, Ktl + ki);
    split_store(vn, Vh + qi, Vl + qi);
}

// ---------------------------------------------------------------------------
// Causal row softmax; reads S[h][t][0..t], writes split probs.
// Only writes up to the k-tile boundary the PV GEMM (mode 2) will read:
// limit = ((t/128)+1)*128.  Entries in [t+1, limit) are zeroed.
// ---------------------------------------------------------------------------
__global__ void __launch_bounds__(256) softmax_kernel(
    const float* __restrict__ S, bf16* __restrict__ Ph, bf16* __restrict__ Pl)
{
    const int t = blockIdx.x, h = blockIdx.y;
    const size_t base = ((size_t)h * Tt + t) * Tt;
    const float* row = S + base;
    const int n = t + 1;
    const int limit = ((t >> 7) + 1) << 7;   // k-tiles PV actually reads
    const int tid = threadIdx.x;
    __shared__ float red[256];

    float mx = -3.4e38f;
    for (int i = tid; i < n; i += 256) mx = fmaxf(mx, row[i]);
    mx = bred256<true>(mx, red, tid);

    float sum = 0.f;
    for (int i = tid; i < n; i += 256) sum += expf(row[i] - mx);
    sum = bred256<false>(sum, red, tid);
    const float inv = 1.f / sum;

    for (int i = tid; i < limit; i += 256) {
        const float p = (i < n) ? expf(row[i] - mx) * inv : 0.f;
        split_store(p, Ph + base + i, Pl + base + i);
    }
}

// ---------------------------------------------------------------------------
// Launch
// ---------------------------------------------------------------------------
extern "C" void kernel_launch(void* const* d_in, const int* in_sizes, int n_in,
                              void* d_out, int out_size)
{
    const float* hidden    = (const float*)d_in[0];
    const int*   positions = (const int*)d_in[1];
    const float* w_qkv     = (const float*)d_in[2];
    const float* w_o       = (const float*)d_in[3];
    const float* qw        = (const float*)d_in[4];
    const float* kw        = (const float*)d_in[5];
    float* out = (float*)d_out;

    float *qkv, *S, *att;
    bf16 *Hh, *Hl, *Wh, *Wl, *Qh, *Ql, *Kth, *Ktl, *Vh, *Vl, *Ph, *Pl, *Ah, *Al, *Woh, *Wol;
    cudaGetSymbolAddress((void**)&qkv, g_qkv);
    cudaGetSymbolAddress((void**)&S,   g_S);
    cudaGetSymbolAddress((void**)&att, g_att);
    cudaGetSymbolAddress((void**)&Hh,  g_Hh);   cudaGetSymbolAddress((void**)&Hl,  g_Hl);
    cudaGetSymbolAddress((void**)&Wh,  g_Wh);   cudaGetSymbolAddress((void**)&Wl,  g_Wl);
    cudaGetSymbolAddress((void**)&Qh,  g_Qh);   cudaGetSymbolAddress((void**)&Ql,  g_Ql);
    cudaGetSymbolAddress((void**)&Kth, g_Kth);  cudaGetSymbolAddress((void**)&Ktl, g_Ktl);
    cudaGetSymbolAddress((void**)&Vh,  g_Vh);   cudaGetSymbolAddress((void**)&Vl,  g_Vl);
    cudaGetSymbolAddress((void**)&Ph,  g_Ph);   cudaGetSymbolAddress((void**)&Pl,  g_Pl);
    cudaGetSymbolAddress((void**)&Ah,  g_Ah);   cudaGetSymbolAddress((void**)&Al,  g_Al);
    cudaGetSymbolAddress((void**)&Woh, g_Woh);  cudaGetSymbolAddress((void**)&Wol, g_Wol);

    // Unconditional (idempotent; no static guards per harness rules)
    cudaFuncSetAttribute(gemm3_kernel,
                         cudaFuncAttributeMaxDynamicSharedMemorySize, SMEM_BYTES);

    // 1. split inputs / weights to bf16 hi/lo
    split_kernel<<<512, 256>>>(hidden, Hh, Hl, (size_t)Tt * HID);
    split_kernel<<<2048, 256>>>(w_qkv, Wh, Wl, (size_t)HID * QKVN);
    split_kernel<<<1024, 256>>>(w_o, Woh, Wol, (size_t)HID * HID);

    // 2. qkv = hidden @ w_qkv
    gemm3_kernel<<<dim3(QKVN / 128, Tt / 128, 1), 256, SMEM_BYTES>>>(
        Hh, Hl, Wh, Wl, qkv, Tt, QKVN, HID, HID, QKVN, QKVN, 0, 0, 0, 0);

    // 3. rmsnorm + rope, write split Q / K^T / V
    normrope_kernel<<<dim3(Tt, NH), 256>>>(qkv, positions, qw, kw,
                                           Qh, Ql, Kth, Ktl, Vh, Vl);

    // 4. scores[h] = Q[h] @ K[h]^T  (skip tiles above diagonal)
    gemm3_kernel<<<dim3(Tt / 128, Tt / 128, NH), 256, SMEM_BYTES>>>(
        Qh, Ql, Kth, Ktl, S, Tt, Tt, HD, HD, Tt, Tt,
        (long long)Tt * HD, (long long)HD * Tt, (long long)Tt * Tt, 1);

    // 5. causal softmax -> split probs
    softmax_kernel<<<dim3(Tt, NH), 256>>>(S, Ph, Pl);

    // 6. attn[h] = P[h] @ V[h]  (k-tiles limited by diagonal)
    gemm3_kernel<<<dim3(HD / 128, Tt / 128, NH), 256, SMEM_BYTES>>>(
        Ph, Pl, Vh, Vl, att, Tt, HD, Tt, Tt, HD, HID,
        (long long)Tt * Tt, (long long)Tt * HD, (long long)HD, 2);

    // 7. out = attn @ w_o
    split_kernel<<<512, 256>>>(att, Ah, Al, (size_t)Tt * HID);
    gemm3_kernel<<<dim3(HID / 128, Tt / 128, 1), 256, SMEM_BYTES>>>(
        Ah, Al, Woh, Wol, out, Tt, HID, HID, HID, HID, HID, 0, 0, 0, 0);
}